// round 1
// baseline (speedup 1.0000x reference)
#include <cuda_runtime.h>
#include <cuda_bf16.h>

#define K_FEAT 4096
#define N_CTRL 256
#define M_INT  254   // interior knots (n-2)

// Scratch (no allocations allowed in kernel_launch): ~8.3 MB static device mem.
__device__ float g_dp[M_INT * K_FEAT];
__device__ float g_gamma[N_CTRL * K_FEAT];

// ---------------------------------------------------------------------------
// Kernel 1: per-column Thomas solve of the natural-spline tridiagonal system.
//   [1 4 1] g = 6*(n-1)^2 * second_difference(values)
// Pivots cp[i] are data-independent (uniform knots): cp[0]=1/4,
// cp[i]=1/(4-cp[i-1]) -> converges to 2-sqrt(3) within fp32 by i~12.
// One thread per feature column; rows read/written coalesced.
// ---------------------------------------------------------------------------
__global__ void __launch_bounds__(128) spline_solve_kernel(const float* __restrict__ values) {
    __shared__ float cp[M_INT];
    const int tid = threadIdx.x;
    if (tid == 0) {
        float c = 0.25f;
        cp[0] = c;
        #pragma unroll
        for (int i = 1; i < 24; i++) { c = 1.0f / (4.0f - c); cp[i] = c; }
    }
    for (int i = 24 + tid; i < M_INT; i += blockDim.x)
        cp[i] = 0.26794919243112270647f;   // 2 - sqrt(3), fixed point of recurrence
    __syncthreads();

    const int k = blockIdx.x * blockDim.x + tid;   // grid covers exactly K_FEAT

    const float C2 = 6.0f * 255.0f * 255.0f;       // 6/h^2, h = 1/(n-1)
    float v0 = values[k];
    float v1 = values[K_FEAT + k];
    float dp = 0.0f;
    for (int i = 0; i < M_INT; i++) {
        float v2  = values[(size_t)(i + 2) * K_FEAT + k];
        float rhs = C2 * ((v2 - v1) - (v1 - v0));
        dp = (rhs - dp) * cp[i];                   // i=0: dp_prev=0, cp[0]=1/4 -> rhs/4
        g_dp[(size_t)i * K_FEAT + k] = dp;
        v0 = v1; v1 = v2;
    }

    // Backward substitution: g[i] = dp[i] - cp[i]*g[i+1]
    float g = dp;                                   // dp[M_INT-1]
    g_gamma[(size_t)M_INT * K_FEAT + k] = g;        // gamma row 254
    for (int i = M_INT - 2; i >= 0; i--) {
        g = fmaf(-cp[i], g, g_dp[(size_t)i * K_FEAT + k]);
        g_gamma[(size_t)(i + 1) * K_FEAT + k] = g;
    }
    g_gamma[k] = 0.0f;                              // natural BCs: gamma[0]=gamma[n-1]=0
    g_gamma[(size_t)(N_CTRL - 1) * K_FEAT + k] = 0.0f;
}

// ---------------------------------------------------------------------------
// Kernel 2: evaluation. One thread owns (segment s, one float4 of k).
// It loads y0,y1,gamma0,gamma1 into registers ONCE, then loops over the ~32
// eval points whose parameter t falls in segment s. This turns a would-be
// L2-bound gather (536 MB reads) into a pure DRAM-write-bound stream.
// Integer partition: j in segment s  <=>  floor(j*255/ne1) == s  (j=ne1 -> 254).
// ---------------------------------------------------------------------------
__global__ void __launch_bounds__(256) spline_eval_kernel(
    const float* __restrict__ values, float* __restrict__ out, int ne1) {

    const int s  = blockIdx.y;                               // 0..254
    const int k  = (blockIdx.x * blockDim.x + threadIdx.x) * 4;

    const float4 y0 = *reinterpret_cast<const float4*>(values  + (size_t)s       * K_FEAT + k);
    const float4 y1 = *reinterpret_cast<const float4*>(values  + (size_t)(s + 1) * K_FEAT + k);
    const float4 q0 = *reinterpret_cast<const float4*>(g_gamma + (size_t)s       * K_FEAT + k);
    const float4 q1 = *reinterpret_cast<const float4*>(g_gamma + (size_t)(s + 1) * K_FEAT + k);

    const int jstart = (s * ne1 + 254) / 255;                // ceil(s*ne1/255)
    const int jend   = (s < 254) ? ((s + 1) * ne1 + 254) / 255 - 1 : ne1;

    const float inv_ne1 = 1.0f / (float)ne1;
    const float w = 1.0f / (6.0f * 255.0f * 255.0f);         // h^2/6

    const int base = s * ne1;
    for (int j = jstart; j <= jend; j++) {
        float b  = (float)(j * 255 - base) * inv_ne1;        // in [0,1]
        float a  = 1.0f - b;
        float wa = (a * a * a - a) * w;
        float wb = (b * b * b - b) * w;
        float4 o;
        o.x = fmaf(a, y0.x, fmaf(b, y1.x, fmaf(wa, q0.x, wb * q1.x)));
        o.y = fmaf(a, y0.y, fmaf(b, y1.y, fmaf(wa, q0.y, wb * q1.y)));
        o.z = fmaf(a, y0.z, fmaf(b, y1.z, fmaf(wa, q0.z, wb * q1.z)));
        o.w = fmaf(a, y0.w, fmaf(b, y1.w, fmaf(wa, q0.w, wb * q1.w)));
        *reinterpret_cast<float4*>(out + (size_t)j * K_FEAT + k) = o;
    }
}

extern "C" void kernel_launch(void* const* d_in, const int* in_sizes, int n_in,
                              void* d_out, int out_size) {
    const float* values = (const float*)d_in[0];
    float* out = (float*)d_out;

    const int n_eval = out_size / K_FEAT;   // derived from harness; avoids device scalar read
    const int ne1 = n_eval - 1;

    spline_solve_kernel<<<K_FEAT / 128, 128>>>(values);

    dim3 grid(K_FEAT / (256 * 4), N_CTRL - 1);   // (4, 255)
    spline_eval_kernel<<<grid, 256>>>(values, out, ne1);
}

// round 2
// speedup vs baseline: 1.8429x; 1.8429x over previous
#include <cuda_runtime.h>
#include <cuda_bf16.h>

#define K_FEAT 4096
#define N_CTRL 256
#define M_INT  254   // interior knots (n-2)
#define CHUNK  32    // interior rows per solver chunk
#define HALO   16    // overlap; pivot fixed point 2-sqrt(3): err ~ 0.268^16 ~ 7e-10

// Scratch (no allocations allowed): gamma only, 4 MB static device mem.
__device__ float g_gamma[N_CTRL * K_FEAT];

// ---------------------------------------------------------------------------
// Kernel 1: halo-overlapped parallel Thomas solve of [1 4 1] g = 6/h^2 * d2(v).
// The forward pivots cp[i] are data-independent (uniform knots) and converge
// to 2-sqrt(3) by i~12, so influence decays ~0.268/row. Each thread owns one
// (chunk of 32 interior rows, column): forward sweep starts HALO rows early
// with dp=0, backward sweep starts HALO rows late with g=0. Fully unrolled ->
// the 48-entry dp scratch lives in registers; no global scratch round-trip.
// Grid: (K_FEAT/256, 8) = 128 blocks of 256 -> ~1 block/SM.
// ---------------------------------------------------------------------------
__global__ void __launch_bounds__(256) spline_solve_kernel(const float* __restrict__ values) {
    __shared__ float cp[M_INT];
    const int tid = threadIdx.x;
    if (tid == 0) {
        float c = 0.25f;
        cp[0] = c;
        #pragma unroll
        for (int i = 1; i < 24; i++) { c = 1.0f / (4.0f - c); cp[i] = c; }
    }
    for (int i = 24 + tid; i < M_INT; i += 256)
        cp[i] = 0.26794919243112270647f;   // 2 - sqrt(3)
    __syncthreads();

    const int k  = blockIdx.x * 256 + tid;       // feature column
    const int c0 = blockIdx.y * CHUNK;           // first interior row of chunk
    const int lo = c0 - HALO;

    const float C2 = 6.0f * 255.0f * 255.0f;     // 6/h^2
    const int first = lo < 0 ? 0 : lo;
    float v0 = values[(size_t)first * K_FEAT + k];
    float v1 = values[(size_t)(first + 1) * K_FEAT + k];
    float dp = 0.0f;
    float dploc[CHUNK + HALO];                   // register array (const indices)

    #pragma unroll
    for (int u = 0; u < CHUNK + 2 * HALO; u++) {
        const int i = lo + u;
        if (i >= 0 && i < M_INT) {
            float v2  = values[(size_t)(i + 2) * K_FEAT + k];
            float rhs = C2 * ((v2 - v1) - (v1 - v0));
            dp = (rhs - dp) * cp[i];
            if (u >= HALO) dploc[u - HALO] = dp; // rows >= c0
            v0 = v1; v1 = v2;
        }
    }

    // Backward: g[i] = dp[i] - cp[i]*g[i+1], seeded with g=0 HALO rows above.
    float g = 0.0f;
    #pragma unroll
    for (int u = CHUNK + 2 * HALO - 1; u >= HALO; u--) {
        const int i = lo + u;                    // i >= c0 here
        if (i < M_INT) {
            g = fmaf(-cp[i], g, dploc[u - HALO]);
            if (u < HALO + CHUNK)                // rows inside this chunk
                g_gamma[(size_t)(i + 1) * K_FEAT + k] = g;
        }
    }

    // Natural BCs
    if (blockIdx.y == 0)              g_gamma[k] = 0.0f;
    if (blockIdx.y == gridDim.y - 1)  g_gamma[(size_t)(N_CTRL - 1) * K_FEAT + k] = 0.0f;
}

// ---------------------------------------------------------------------------
// Kernel 2: evaluation. One thread owns (segment s, one float4 of k); loads
// y0,y1,gamma0,gamma1 into registers once, loops over the ~32 eval points in
// that segment. Streaming (evict-first) stores: output is write-once, keep
// L2 for values/gamma.
// ---------------------------------------------------------------------------
__global__ void __launch_bounds__(256) spline_eval_kernel(
    const float* __restrict__ values, float* __restrict__ out, int ne1) {

    const int s = blockIdx.y;                                // 0..254
    const int k = (blockIdx.x * blockDim.x + threadIdx.x) * 4;

    const float4 y0 = *reinterpret_cast<const float4*>(values  + (size_t)s       * K_FEAT + k);
    const float4 y1 = *reinterpret_cast<const float4*>(values  + (size_t)(s + 1) * K_FEAT + k);
    const float4 q0 = *reinterpret_cast<const float4*>(g_gamma + (size_t)s       * K_FEAT + k);
    const float4 q1 = *reinterpret_cast<const float4*>(g_gamma + (size_t)(s + 1) * K_FEAT + k);

    const int jstart = (s * ne1 + 254) / 255;                // ceil(s*ne1/255)
    const int jend   = (s < 254) ? ((s + 1) * ne1 + 254) / 255 - 1 : ne1;

    const float inv_ne1 = 1.0f / (float)ne1;
    const float w = 1.0f / (6.0f * 255.0f * 255.0f);         // h^2/6
    const int base = s * ne1;

    #pragma unroll 4
    for (int j = jstart; j <= jend; j++) {
        float b  = (float)(j * 255 - base) * inv_ne1;        // in [0,1]
        float a  = 1.0f - b;
        float wa = (a * a * a - a) * w;
        float wb = (b * b * b - b) * w;
        float4 o;
        o.x = fmaf(a, y0.x, fmaf(b, y1.x, fmaf(wa, q0.x, wb * q1.x)));
        o.y = fmaf(a, y0.y, fmaf(b, y1.y, fmaf(wa, q0.y, wb * q1.y)));
        o.z = fmaf(a, y0.z, fmaf(b, y1.z, fmaf(wa, q0.z, wb * q1.z)));
        o.w = fmaf(a, y0.w, fmaf(b, y1.w, fmaf(wa, q0.w, wb * q1.w)));
        __stcs(reinterpret_cast<float4*>(out + (size_t)j * K_FEAT + k), o);
    }
}

extern "C" void kernel_launch(void* const* d_in, const int* in_sizes, int n_in,
                              void* d_out, int out_size) {
    const float* values = (const float*)d_in[0];
    float* out = (float*)d_out;

    const int n_eval = out_size / K_FEAT;
    const int ne1 = n_eval - 1;

    dim3 sgrid(K_FEAT / 256, (M_INT + CHUNK - 1) / CHUNK);   // (16, 8)
    spline_solve_kernel<<<sgrid, 256>>>(values);

    dim3 egrid(K_FEAT / (256 * 4), N_CTRL - 1);              // (4, 255)
    spline_eval_kernel<<<egrid, 256>>>(values, out, ne1);
}

// round 5
// speedup vs baseline: 2.0597x; 1.1176x over previous
#include <cuda_runtime.h>
#include <cuda_bf16.h>

#define K_FEAT 4096
#define N_CTRL 256
#define M_INT  254      // interior knots
#define SEG    2        // segments per block
#define TAPS   29       // convolution window: j in [s0-14, s0+14]
#define PMAX   64       // signed-power table size (zeros beyond 48)

// ---------------------------------------------------------------------------
// Single fused kernel. The natural-spline system [1 4 1] g = (6/h^2) d2(v) on
// uniform knots has a closed-form inverse: (M^-1)_{pj} = A*rho^|p-j| with
// rho = -(2-sqrt(3)), A = 1/(2*sqrt(3)), plus exponentially small boundary
// image terms -A*rho^(p+j+2) (left) and -A*rho^(2m-p-j) (right). Influence
// decays 0.268/row, so a 29-tap truncated convolution gives gamma to ~1e-8.
//
// Each block owns (2 segments, 1024 feature cols). It computes gamma rows
// s0, s0+1, s0+2 as convolutions of second differences (weights are
// block-uniform, staged in smem), then evaluates & streams the ~64 output
// rows. One launch: no solve kernel, no scratch, no inter-kernel gap.
// ---------------------------------------------------------------------------
__global__ void __launch_bounds__(256) spline_fused_kernel(
    const float* __restrict__ values, float* __restrict__ out, int ne1) {

    __shared__ float P[PMAX];          // signed powers rho^d (0 for d>=48)
    __shared__ float wA[TAPS], wB[TAPS], wC[TAPS];

    const int tid = threadIdx.x;
    const int s0  = blockIdx.y * SEG;              // first segment (0..254)
    const int jlo = s0 - 14;                       // first tap (interior row)

    // --- build weight tables (block-uniform scalars) ---
    if (tid == 0) {
        const float rho = -0.26794919243112270647f;   // -(2-sqrt(3))
        float p = 1.0f;
        #pragma unroll
        for (int d = 0; d < 48; d++) { P[d] = p; p *= rho; }
        #pragma unroll
        for (int d = 48; d < PMAX; d++) P[d] = 0.0f;
    }
    __syncthreads();
    if (tid < TAPS) {
        const float ACP = 0.28867513459481288225f * 6.0f * 255.0f * 255.0f; // A*6/h^2
        const int j = jlo + tid;
        // weight for interior gamma index p at tap j (finite matrix w/ images)
        #define WEIGHT(p) \
            ((j >= 0 && j < M_INT && (p) >= 0 && (p) < M_INT) \
                ? ACP * (P[abs(j-(p))] - P[min(j+(p)+2, PMAX-1)] \
                         - P[min(2*M_INT - j - (p), PMAX-1)]) : 0.0f)
        wA[tid] = WEIGHT(s0 - 1);   // -> gamma[s0]
        wB[tid] = WEIGHT(s0);       // -> gamma[s0+1]
        wC[tid] = WEIGHT(s0 + 1);   // -> gamma[s0+2]
        #undef WEIGHT
    }
    __syncthreads();

    const int k = (blockIdx.x * 256 + tid) * 4;    // this thread's 4 columns
    #define VROW(r) (*reinterpret_cast<const float4*>(values + (size_t)(r) * K_FEAT + k))

    // --- gamma via 29-tap convolution of second differences ---
    const int first = jlo < 0 ? 0 : jlo;
    float4 v0 = VROW(first);
    float4 v1 = VROW(first + 1);
    float4 qa = {0,0,0,0}, qb = {0,0,0,0}, qc = {0,0,0,0};

    #pragma unroll
    for (int u = 0; u < TAPS; u++) {
        const int j = jlo + u;
        if (j >= 0 && j < M_INT) {
            float4 v2 = VROW(j + 2);
            float rx = (v2.x - v1.x) - (v1.x - v0.x);
            float ry = (v2.y - v1.y) - (v1.y - v0.y);
            float rz = (v2.z - v1.z) - (v1.z - v0.z);
            float rw = (v2.w - v1.w) - (v1.w - v0.w);
            float a = wA[u], b = wB[u], c = wC[u];
            qa.x = fmaf(a, rx, qa.x); qa.y = fmaf(a, ry, qa.y);
            qa.z = fmaf(a, rz, qa.z); qa.w = fmaf(a, rw, qa.w);
            qb.x = fmaf(b, rx, qb.x); qb.y = fmaf(b, ry, qb.y);
            qb.z = fmaf(b, rz, qb.z); qb.w = fmaf(b, rw, qb.w);
            qc.x = fmaf(c, rx, qc.x); qc.y = fmaf(c, ry, qc.y);
            qc.z = fmaf(c, rz, qc.z); qc.w = fmaf(c, rw, qc.w);
            v0 = v1; v1 = v2;
        }
    }

    // --- evaluate & stream both segments ---
    const float inv_ne1 = 1.0f / (float)ne1;
    const float w = 1.0f / (6.0f * 255.0f * 255.0f);   // h^2/6

    #pragma unroll
    for (int seg = 0; seg < SEG; seg++) {
        const int s = s0 + seg;
        if (s > 254) break;
        const float4 y0 = VROW(s);
        const float4 y1 = VROW(s + 1);
        const float4 q0 = seg ? qb : qa;
        const float4 q1 = seg ? qc : qb;

        const int jstart = (s * ne1 + 254) / 255;                  // ceil
        const int jend   = (s < 254) ? ((s + 1) * ne1 + 254) / 255 - 1 : ne1;
        const int base   = s * ne1;

        #pragma unroll 4
        for (int j = jstart; j <= jend; j++) {
            float b  = (float)(j * 255 - base) * inv_ne1;          // in [0,1]
            float a  = 1.0f - b;
            float wa = (a * a * a - a) * w;
            float wb = (b * b * b - b) * w;
            float4 o;
            o.x = fmaf(a, y0.x, fmaf(b, y1.x, fmaf(wa, q0.x, wb * q1.x)));
            o.y = fmaf(a, y0.y, fmaf(b, y1.y, fmaf(wa, q0.y, wb * q1.y)));
            o.z = fmaf(a, y0.z, fmaf(b, y1.z, fmaf(wa, q0.z, wb * q1.z)));
            o.w = fmaf(a, y0.w, fmaf(b, y1.w, fmaf(wa, q0.w, wb * q1.w)));
            __stcs(reinterpret_cast<float4*>(out + (size_t)j * K_FEAT + k), o);
        }
    }
    #undef VROW
}

extern "C" void kernel_launch(void* const* d_in, const int* in_sizes, int n_in,
                              void* d_out, int out_size) {
    const float* values = (const float*)d_in[0];
    float* out = (float*)d_out;

    const int n_eval = out_size / K_FEAT;
    const int ne1 = n_eval - 1;

    dim3 grid(K_FEAT / (256 * 4), (N_CTRL - 1 + SEG - 1) / SEG);   // (4, 128)
    spline_fused_kernel<<<grid, 256>>>(values, out, ne1);
}